// round 14
// baseline (speedup 1.0000x reference)
#include <cuda_runtime.h>
#include <math.h>

#define BB 8
#define NN 150
#define SS 22
#define EE 299
#define BN (BB*NN)
#define HNN (NN/2)

// ---------------- persistent scratch (no allocation allowed) ----------------
__device__ __align__(16) float g_h[2][BN*64];
__device__ __align__(16) float g_q[2][BN*4];
__device__ __align__(16) float g_x[2][BN*4];
__device__ __align__(16) float g_A[2][BN*32];
__device__ __align__(16) float g_B[2][BN*32];
__device__ __align__(16) float g_aq[2][BN*6];     // A_i @ Wq (bm folded into A)
__device__ __align__(16) float g_bqv[2][BN*8];    // B_j @ Wq (padded stride 8)
__device__ __align__(16) float g_eq[4][EE*8];     // Wm_E rows @ Wq (padded stride 8)
__device__ __align__(16) float g_Gt[4][72];       // (Wg @ Wq) transposed: [c*12 + r]
__device__ __align__(16) float g_P[4][EE*32];     // scratch: prefix of Wm_E rows
__device__ __align__(16) float g_Esum[4][NN*32];  // per-i window sum of E rows minus diag row

// ---------------- quaternion helpers (match reference exactly) --------------
__device__ __forceinline__ void qmul(const float a[4], const float b[4], float o[4]) {
    o[0] = a[0]*b[0] - a[1]*b[1] - a[2]*b[2] - a[3]*b[3];
    o[1] = a[0]*b[1] + a[1]*b[0] + a[2]*b[3] - a[3]*b[2];
    o[2] = a[0]*b[2] - a[1]*b[3] + a[2]*b[0] + a[3]*b[1];
    o[3] = a[0]*b[3] + a[1]*b[2] - a[2]*b[1] + a[3]*b[0];
}
__device__ __forceinline__ void qrot(const float q[4], const float v[3], float o[3]) {
    float tx = 2.f*(q[2]*v[2] - q[3]*v[1]);
    float ty = 2.f*(q[3]*v[0] - q[1]*v[2]);
    float tz = 2.f*(q[1]*v[1] - q[2]*v[0]);
    o[0] = v[0] + q[0]*tx + (q[2]*tz - q[3]*ty);
    o[1] = v[1] + q[0]*ty + (q[3]*tx - q[1]*tz);
    o[2] = v[2] + q[0]*tz + (q[1]*ty - q[2]*tx);
}

// ---- multi-value butterfly reduction step: keep HALF values, ship HALF ----
template<int O, int HALF>
__device__ __forceinline__ void rstep(float* a, int lane) {
    bool hi = (lane & O) != 0;
    #pragma unroll
    for (int i = 0; i < HALF; i++) {
        float send = hi ? a[i] : a[i+HALF];
        float got = __shfl_xor_sync(0xffffffffu, send, O);
        a[i] = (hi ? a[i+HALF] : a[i]) + got;
    }
}

// ---- dual pair core: nodes i0,i1 vs same j; Gt via float4 broadcast LDS ----
template<bool LAST>
__device__ __forceinline__ void pair_core2(
    const float qi0[4], const float xi0[3],
    const float qi1[4], const float xi1[3],
    const float qj[4],  const float xj[3],
    const float* __restrict__ eq0row, const float* __restrict__ eq1row,
    float4 v0, float4 v1,
    const float* __restrict__ s_aq0, const float* __restrict__ s_aq1,
    const float* __restrict__ bqs, const float* __restrict__ sGt,
    float mmf0, float mmf1, float* acc)
{
    constexpr int NPA = LAST ? 7 : 16;
    constexpr int XO  = LAST ? 0 : 9;

    float qji[4] = {qj[0],-qj[1],-qj[2],-qj[3]};

    float diff0[3] = {xi0[0]-xj[0], xi0[1]-xj[1], xi0[2]-xj[2]};
    float lx0[3]; qrot(qji, diff0, lx0);
    float tq0[4]; qmul(qji, qi0, tq0);
    float lq0[4]; qmul(tq0, qj, lq0);
    float d20 = diff0[0]*diff0[0]+diff0[1]*diff0[1]+diff0[2]*diff0[2];
    float dq0 = fabsf(qi0[0]*qj[0]+qi0[1]*qj[1]+qi0[2]*qj[2]+qi0[3]*qj[3]);
    float geo0[9] = {lx0[0],lx0[1],lx0[2],lq0[0],lq0[1],lq0[2],lq0[3],d20,dq0};

    float diff1[3] = {xi1[0]-xj[0], xi1[1]-xj[1], xi1[2]-xj[2]};
    float lx1[3]; qrot(qji, diff1, lx1);
    float tq1[4]; qmul(qji, qi1, tq1);
    float lq1[4]; qmul(tq1, qj, lq1);
    float d21 = diff1[0]*diff1[0]+diff1[1]*diff1[1]+diff1[2]*diff1[2];
    float dq1 = fabsf(qi1[0]*qj[0]+qi1[1]*qj[1]+qi1[2]*qj[2]+qi1[3]*qj[3]);
    float geo1[9] = {lx1[0],lx1[1],lx1[2],lq1[0],lq1[1],lq1[2],lq1[3],d21,dq1};

    const float4* e0p = reinterpret_cast<const float4*>(eq0row);
    float4 a0 = e0p[0], a1 = e0p[1];
    const float4* e1p = reinterpret_cast<const float4*>(eq1row);
    float4 b0 = e1p[0], b1 = e1p[1];
    float basec0[6] = {a0.x+v0.x, a0.y+v0.y, a0.z+v0.z, a0.w+v0.w, a1.x+v1.x, a1.y+v1.y};
    float basec1[6] = {b0.x+v0.x, b0.y+v0.y, b0.z+v0.z, b0.w+v0.w, b1.x+v1.x, b1.y+v1.y};

    const float4* sg4 = reinterpret_cast<const float4*>(sGt);
    float del0[6], del1[6];
    #pragma unroll
    for (int c = 0; c < 6; c++) {
        float bc = bqs[c];
        float u0 = s_aq0[c] + bc + basec0[c];
        float u1 = s_aq1[c] + bc + basec1[c];
        float4 gA = sg4[c*3], gB = sg4[c*3+1], gC = sg4[c*3+2];
        float g[9] = {gA.x,gA.y,gA.z,gA.w,gB.x,gB.y,gB.z,gB.w,gC.x};
        #pragma unroll
        for (int r = 0; r < 9; r++) {
            u0 = fmaf(geo0[r], g[r], u0);
            u1 = fmaf(geo1[r], g[r], u1);
        }
        del0[c] = u0 * mmf0;
        del1[c] = u1 * mmf1;
    }

    {
        float v3[3] = {lx0[0]+del0[3], lx0[1]+del0[4], lx0[2]+del0[5]};
        float rx[3]; qrot(qj, v3, rx);
        float vq[4] = {0.f, del0[0], del0[1], del0[2]};
        float sq[4]; qmul(lq0, vq, sq);
        if (!LAST) {
            #pragma unroll
            for (int r = 0; r < 9; r++) acc[r] = geo0[r] * mmf0;
        }
        acc[XO+0] = rx[0]+xj[0]; acc[XO+1] = rx[1]+xj[1]; acc[XO+2] = rx[2]+xj[2];
        acc[XO+3] = lq0[0]+sq[0]; acc[XO+4] = lq0[1]+sq[1];
        acc[XO+5] = lq0[2]+sq[2]; acc[XO+6] = lq0[3]+sq[3];
    }
    {
        float* a = acc + NPA;
        float v3[3] = {lx1[0]+del1[3], lx1[1]+del1[4], lx1[2]+del1[5]};
        float rx[3]; qrot(qj, v3, rx);
        float vq[4] = {0.f, del1[0], del1[1], del1[2]};
        float sq[4]; qmul(lq1, vq, sq);
        if (!LAST) {
            #pragma unroll
            for (int r = 0; r < 9; r++) a[r] = geo1[r] * mmf1;
        }
        a[XO+0] = rx[0]+xj[0]; a[XO+1] = rx[1]+xj[1]; a[XO+2] = rx[2]+xj[2];
        a[XO+3] = lq1[0]+sq[0]; a[XO+4] = lq1[1]+sq[1];
        a[XO+5] = lq1[2]+sq[2]; a[XO+6] = lq1[3]+sq[3];
    }
}

// ---------------- merged init + weight prep (prep split 3-way/layer) ---------
__global__ void k_initprep(const float* __restrict__ quats, const float* __restrict__ trans,
                           const float* __restrict__ feat, const int* __restrict__ tptr,
                           const float* __restrict__ bm1,
                           const float* wm1, const float* wm2, const float* wm3, const float* wm4,
                           const float* wq1, const float* wq2, const float* wq3, const float* wq4) {
    int t = threadIdx.x; // 128
    if (blockIdx.x < BN) {
        int n = blockIdx.x;
        __shared__ float hs[30];
        __shared__ float sAB[64];
        float tv = tptr ? (float)(*tptr) : 250.0f;
        float ft = tv * (1.0f/1000.0f);
        if (t < 4)  { float v = quats[n*4+t]; g_q[0][n*4+t] = v; g_h[0][n*64+t] = v; hs[t] = v; }
        if (t < 3)  { float v = trans[n*3+t]; g_x[0][n*4+t] = v; g_h[0][n*64+4+t] = v; hs[4+t] = v; }
        if (t == 3) g_x[0][n*4+3] = 0.f;
        if (t < SS) { float v = feat[n*SS+t]; g_h[0][n*64+7+t] = v; hs[7+t] = v; }
        if (t == 0) { g_h[0][n*64+29] = ft; hs[29] = ft; }
        __syncthreads();
        if (t < 64) {
            int k = t & 31;
            float v = (t < 32) ? bm1[k] : 0.f;
            const float* base = wm1 + ((t < 32) ? 0 : 30*32);
            #pragma unroll
            for (int r = 0; r < 30; r++) v = fmaf(hs[r], base[r*32+k], v);
            sAB[t] = v;
            if (t < 32) g_A[0][n*32+k] = v; else g_B[0][n*32+k] = v;
        }
        __syncthreads();
        if (t < 6) {
            float v = 0.f;
            #pragma unroll
            for (int k = 0; k < 32; k++) v = fmaf(sAB[k], wq1[k*6+t], v);
            g_aq[0][n*6+t] = v;
        } else if (t >= 8 && t < 16) {
            int c = t - 8;
            float v = 0.f;
            if (c < 6) {
                #pragma unroll
                for (int k = 0; k < 32; k++) v = fmaf(sAB[32+k], wq1[k*6+c], v);
            }
            g_bqv[0][n*8+c] = v;
        }
    } else {
        int pb = blockIdx.x - BN;     // 0..11
        int l = pb / 3, part = pb - l*3;
        const float* wm = (l==0)?wm1:(l==1)?wm2:(l==2)?wm3:wm4;
        const float* wq = (l==0)?wq1:(l==1)?wq2:(l==2)?wq3:wq4;
        int H = (l==0)?30:64;
        const float* wmE = wm + 2*H*32;
        const float* wg  = wm + (2*H+EE)*32;
        if (part == 0) {
            // eq rows [0,150)
            for (int idx = t; idx < 150*6; idx += 128) {
                int r = idx / 6, c = idx - r*6;
                float v = 0.f;
                #pragma unroll
                for (int k = 0; k < 32; k++) v = fmaf(wmE[r*32+k], wq[k*6+c], v);
                g_eq[l][r*8+c] = v;
            }
            for (int r = t; r < 150; r += 128) { g_eq[l][r*8+6] = 0.f; g_eq[l][r*8+7] = 0.f; }
        } else if (part == 1) {
            // eq rows [150,299) + Gt
            for (int idx = t; idx < 149*6; idx += 128) {
                int r = 150 + idx / 6, c = idx % 6;
                float v = 0.f;
                #pragma unroll
                for (int k = 0; k < 32; k++) v = fmaf(wmE[r*32+k], wq[k*6+c], v);
                g_eq[l][r*8+c] = v;
            }
            for (int r = 150 + t; r < EE; r += 128) { g_eq[l][r*8+6] = 0.f; g_eq[l][r*8+7] = 0.f; }
            if (t < 72) {
                int c = t / 12, r = t - c*12;
                float v = 0.f;
                if (r < 9) {
                    #pragma unroll
                    for (int k = 0; k < 32; k++) v = fmaf(wg[r*32+k], wq[k*6+c], v);
                }
                g_Gt[l][t] = v;
            }
        } else {
            // prefix + Esum
            if (t < 32) {
                float run = 0.f;
                for (int r = 0; r < EE; r++) { run += wmE[r*32+t]; g_P[l][r*32+t] = run; }
            }
            __syncthreads();
            for (int idx = t; idx < NN*32; idx += 128) {
                int i = idx >> 5, k = idx & 31;
                float v = g_P[l][(i+NN-1)*32+k]
                        - (i ? g_P[l][(i-1)*32+k] : 0.f)
                        - wmE[(NN-1)*32+k];
                g_Esum[l][idx] = v;
            }
        }
    }
}

// ---------------- pair kernel: one block per (b, node-pair) ------------------
template<int H, bool LAST>
__global__ void __launch_bounds__(160) k_pair2(int p, int lidx,
    const float* __restrict__ wm,  const float* __restrict__ bq,
    const float* __restrict__ wf,  const float* __restrict__ bf,
    const float* __restrict__ bm2, const float* __restrict__ wm2,
    const float* __restrict__ wq2, float* __restrict__ out)
{
    const int blk = blockIdx.x;                 // 600
    const int b = blk / HNN, ii = blk - b*HNN;
    const int i0 = 2*ii, i1 = i0+1;
    const int node0 = b*NN + i0, node1 = node0+1;
    const int tid = threadIdx.x;

    constexpr int NPA  = LAST ? 7 : 16;
    constexpr int NRED = LAST ? 16 : 32;
    constexpr int NFIN = 2*NPA;
    constexpr int XO   = LAST ? 0 : 9;

    __shared__ float4 qs[NN], xs[NN];
    __shared__ float sA0[32], sBi0[32], sA1[32], sBi1[32];
    __shared__ __align__(16) float sGt[72];
    __shared__ float s_aq0[6], s_aq1[6], bqs[6];
    __shared__ float hs0[64], hs1[64];
    __shared__ float red[5][32];
    __shared__ float fin[32];
    __shared__ float sb[5][32];
    __shared__ float msum0[32], msum1[32];
    __shared__ float hn0[64], hn1[64];
    __shared__ float sAB0[64], sAB1[64];

    // ---- staged loads (R8/R11-proven) ----
    {
        const float4* q4 = reinterpret_cast<const float4*>(g_q[p]) + b*NN;
        const float4* x4 = reinterpret_cast<const float4*>(g_x[p]) + b*NN;
        for (int idx = tid; idx < NN; idx += 160) { qs[idx] = q4[idx]; xs[idx] = x4[idx]; }
    }
    if (tid < 18) reinterpret_cast<float4*>(sGt)[tid] =
        reinterpret_cast<const float4*>(g_Gt[lidx])[tid];
    if (tid >= 64 && tid < 70)  s_aq0[tid-64] = g_aq[p][node0*6+(tid-64)];
    if (tid >= 70 && tid < 76)  s_aq1[tid-70] = g_aq[p][node1*6+(tid-70)];
    if (tid >= 76 && tid < 82)  bqs[tid-76]   = bq[tid-76];
    if (!LAST) {
        if (tid >= 96 && tid < 128) { int k = tid-96;  sA0[k] = g_A[p][node0*32+k]; sBi0[k] = g_B[p][node0*32+k]; }
        if (tid >= 128)             { int k = tid-128; sA1[k] = g_A[p][node1*32+k]; sBi1[k] = g_B[p][node1*32+k]; }
        if (tid < 64)               hs0[tid]    = g_h[p][node0*64+tid];
        else if (tid < 128)         hs1[tid-64] = g_h[p][node1*64+(tid-64)];
    }
    __syncthreads();

    const int w = tid >> 5, lane = tid & 31;
    if (!LAST) {
        // strided per-warp partial sum of all B_j (hoisted: overlaps pair math)
        float bacc = 0.f;
        #pragma unroll 6
        for (int jj = w; jj < NN; jj += 5) bacc += g_B[p][(b*NN+jj)*32 + lane];
        sb[w][lane] = bacc;
    }

    float acc[NRED];
    #pragma unroll
    for (int r = 0; r < NRED; r++) acc[r] = 0.f;

    const int j = tid;
    if (j < NN) {
        float4 qjv = qs[j]; float qj[4] = {qjv.x, qjv.y, qjv.z, qjv.w};
        float4 xjv = xs[j]; float xj[3] = {xjv.x, xjv.y, xjv.z};
        const float4* bvp = reinterpret_cast<const float4*>(&g_bqv[p][(b*NN+j)*8]);
        float4 v0 = bvp[0], v1 = bvp[1];
        const float* eq0 = &g_eq[lidx][(NN-1+i0-j)*8];

        float4 qi0v = qs[i0]; float qi0[4] = {qi0v.x, qi0v.y, qi0v.z, qi0v.w};
        float4 xi0v = xs[i0]; float xi0[3] = {xi0v.x, xi0v.y, xi0v.z};
        float4 qi1v = qs[i1]; float qi1[4] = {qi1v.x, qi1v.y, qi1v.z, qi1v.w};
        float4 xi1v = xs[i1]; float xi1[3] = {xi1v.x, xi1v.y, xi1v.z};

        pair_core2<LAST>(qi0, xi0, qi1, xi1, qj, xj, eq0, eq0 + 8, v0, v1,
                         s_aq0, s_aq1, bqs, sGt,
                         (j == i0) ? 0.f : 1.f, (j == i1) ? 0.f : 1.f, acc);
    }

    // ---- multi-value butterfly reduction (R8-proven) ----
    if (!LAST) {
        rstep<16,16>(acc, lane);
        rstep<8,8>(acc, lane);
        rstep<4,4>(acc, lane);
        rstep<2,2>(acc, lane);
        rstep<1,1>(acc, lane);
        red[w][lane] = acc[0];
    } else {
        #pragma unroll
        for (int i = 0; i < 16; i++) acc[i] += __shfl_xor_sync(0xffffffffu, acc[i], 1);
        rstep<16,8>(acc, lane);
        rstep<8,4>(acc, lane);
        rstep<4,2>(acc, lane);
        rstep<2,1>(acc, lane);
        if (!(lane & 1)) red[w][lane >> 1] = acc[0];
    }
    __syncthreads();
    if (tid < NFIN)
        fin[tid] = red[0][tid]+red[1][tid]+red[2][tid]+red[3][tid]+red[4][tid];
    __syncthreads();

    // ---- q/x finalize: thread 0 -> node0, thread 32 -> node1 ----
    if (tid == 0 || tid == 32) {
        int nloc   = (tid == 0) ? i0 : i1;
        int nodeg  = (tid == 0) ? node0 : node1;
        const float* f = fin + ((tid == 0) ? 0 : NPA);
        float4 qiv = qs[nloc]; float qi[4] = {qiv.x, qiv.y, qiv.z, qiv.w};
        const float invn = 1.0f/(float)(NN-1);
        float ux[3] = {f[XO+0]*invn, f[XO+1]*invn, f[XO+2]*invn};
        float s0=f[XO+3], s1=f[XO+4], s2=f[XO+5], s3=f[XO+6];
        float ns = sqrtf(s0*s0+s1*s1+s2*s2+s3*s3);
        float inv = 1.f / fmaxf(ns, 1e-12f);
        float luq[4] = {s0*inv, s1*inv, s2*inv, s3*inv};
        float t1[4]; qmul(qi, luq, t1);
        float qc[4] = {qi[0],-qi[1],-qi[2],-qi[3]};
        float uq[4]; qmul(t1, qc, uq);
        if (LAST) {
            out[nodeg*7+0]=uq[0]; out[nodeg*7+1]=uq[1];
            out[nodeg*7+2]=uq[2]; out[nodeg*7+3]=uq[3];
            out[nodeg*7+4]=ux[0]; out[nodeg*7+5]=ux[1]; out[nodeg*7+6]=ux[2];
        } else {
            int nb = p^1;
            g_q[nb][nodeg*4+0]=uq[0]; g_q[nb][nodeg*4+1]=uq[1];
            g_q[nb][nodeg*4+2]=uq[2]; g_q[nb][nodeg*4+3]=uq[3];
            g_x[nb][nodeg*4+0]=ux[0]; g_x[nb][nodeg*4+1]=ux[1];
            g_x[nb][nodeg*4+2]=ux[2]; g_x[nb][nodeg*4+3]=0.f;
        }
    }

    if (!LAST) {
        // ---- E1: msum for both nodes (64 threads) ----
        if (tid < 64) {
            int k = tid & 31;
            bool n1 = (tid >= 32);
            const float* sA  = n1 ? sA1  : sA0;
            const float* sBi = n1 ? sBi1 : sBi0;
            const float* f   = fin + (n1 ? NPA : 0);
            int irow = n1 ? i1 : i0;
            float sB = sb[0][k]+sb[1][k]+sb[2][k]+sb[3][k]+sb[4][k];
            float v = (float)(NN-1)*sA[k] + (sB - sBi[k]) + g_Esum[lidx][irow*32+k];
            const float* wg = wm + (2*H+EE)*32;
            #pragma unroll
            for (int r = 0; r < 9; r++) v = fmaf(f[r], wg[r*32+k], v);
            (n1 ? msum1 : msum0)[k] = v;
        }
        __syncthreads();
        // ---- E2: o = [h, msum] @ Wf + bf -> relu (128 threads, ILP4) ----
        if (tid < 128) {
            int c = tid & 63;
            bool n1 = (tid >= 64);
            const float* hsrc = n1 ? hs1 : hs0;
            const float* msrc = n1 ? msum1 : msum0;
            float a0 = bf[c], a1 = 0.f, a2 = 0.f, a3 = 0.f;
            int r = 0;
            #pragma unroll
            for (; r + 4 <= H; r += 4) {
                a0 = fmaf(hsrc[r+0], wf[(r+0)*64+c], a0);
                a1 = fmaf(hsrc[r+1], wf[(r+1)*64+c], a1);
                a2 = fmaf(hsrc[r+2], wf[(r+2)*64+c], a2);
                a3 = fmaf(hsrc[r+3], wf[(r+3)*64+c], a3);
            }
            #pragma unroll
            for (; r < H; r++) a0 = fmaf(hsrc[r], wf[r*64+c], a0);
            #pragma unroll
            for (int k = 0; k < 32; k += 4) {
                a0 = fmaf(msrc[k+0], wf[(H+k+0)*64+c], a0);
                a1 = fmaf(msrc[k+1], wf[(H+k+1)*64+c], a1);
                a2 = fmaf(msrc[k+2], wf[(H+k+2)*64+c], a2);
                a3 = fmaf(msrc[k+3], wf[(H+k+3)*64+c], a3);
            }
            float hv = fmaxf((a0+a2)+(a1+a3), 0.f);
            int nodeg = n1 ? node1 : node0;
            (n1 ? hn1 : hn0)[c] = hv;
            g_h[p^1][nodeg*64+c] = hv;
        }
        __syncthreads();
        // ---- E3: A'/B' (128 threads, ILP2) ----
        if (tid < 128) {
            int k = tid & 31;
            bool isB = (tid & 32);
            bool n1 = (tid >= 64);
            const float* h = n1 ? hn1 : hn0;
            float u0 = isB ? 0.f : bm2[k], u1 = 0.f;
            const float* base = wm2 + (isB ? 64*32 : 0);
            #pragma unroll
            for (int r = 0; r < 64; r += 2) {
                u0 = fmaf(h[r+0], base[(r+0)*32+k], u0);
                u1 = fmaf(h[r+1], base[(r+1)*32+k], u1);
            }
            float v = u0 + u1;
            int nodeg = n1 ? node1 : node0;
            float* sAB = n1 ? sAB1 : sAB0;
            sAB[isB ? 32+k : k] = v;
            if (isB) g_B[p^1][nodeg*32+k] = v; else g_A[p^1][nodeg*32+k] = v;
        }
        __syncthreads();
        // ---- E4: aq' / bqv' (ILP2) ----
        {
            int base = tid & 63;
            bool n1 = (tid >= 64);
            if (tid < 128) {
                const float* sAB = n1 ? sAB1 : sAB0;
                int nodeg = n1 ? node1 : node0;
                if (base < 6) {
                    float u0 = 0.f, u1 = 0.f;
                    #pragma unroll
                    for (int k = 0; k < 32; k += 2) {
                        u0 = fmaf(sAB[k+0], wq2[(k+0)*6+base], u0);
                        u1 = fmaf(sAB[k+1], wq2[(k+1)*6+base], u1);
                    }
                    g_aq[p^1][nodeg*6+base] = u0 + u1;
                } else if (base >= 8 && base < 16) {
                    int c = base - 8;
                    float v = 0.f;
                    if (c < 6) {
                        float u0 = 0.f, u1 = 0.f;
                        #pragma unroll
                        for (int k = 0; k < 32; k += 2) {
                            u0 = fmaf(sAB[32+k+0], wq2[(k+0)*6+c], u0);
                            u1 = fmaf(sAB[32+k+1], wq2[(k+1)*6+c], u1);
                        }
                        v = u0 + u1;
                    }
                    g_bqv[p^1][nodeg*8+c] = v;
                }
            }
        }
    }
}

// ---------------- host launcher ---------------------------------------------
extern "C" void kernel_launch(void* const* d_in, const int* in_sizes, int n_in,
                              void* d_out, int out_size) {
    const float *quats = nullptr, *trans = nullptr, *feats = nullptr;
    const int* tptr = nullptr;
    int wmI[4] = {-1,-1,-1,-1};
    int maskIdx = -1;
    int n13952 = 0;
    for (int idx = 0; idx < n_in; idx++) {
        int s = in_sizes[idx];
        if      (s == 4800)  quats = (const float*)d_in[idx];
        else if (s == 3600)  trans = (const float*)d_in[idx];
        else if (s == 26400) feats = (const float*)d_in[idx];
        else if (s == 1200)  maskIdx = idx;
        else if (s == 11776) wmI[0] = idx;
        else if (s == 13952 && n13952 < 3) { wmI[1+n13952] = idx; n13952++; }
    }
    if (maskIdx >= 0 && maskIdx+1 < n_in && in_sizes[maskIdx+1] == 1)
        tptr = (const int*)d_in[maskIdx+1];

    const float *wm[4], *bm[4], *wf[4], *bf[4], *wq[4], *bq[4];
    for (int l = 0; l < 4; l++) {
        int base = wmI[l];
        wm[l] = (const float*)d_in[base+0];
        bm[l] = (const float*)d_in[base+1];
        wf[l] = (const float*)d_in[base+2];
        bf[l] = (const float*)d_in[base+3];
        wq[l] = (const float*)d_in[base+4];
        bq[l] = (const float*)d_in[base+5];
    }
    float* out = (float*)d_out;

    k_initprep<<<BN+12, 128>>>(quats, trans, feats, tptr, bm[0],
                               wm[0], wm[1], wm[2], wm[3],
                               wq[0], wq[1], wq[2], wq[3]);

    k_pair2<30,false><<<BB*HNN, 160>>>(0, 0, wm[0], bq[0], wf[0], bf[0], bm[1], wm[1], wq[1], nullptr);
    k_pair2<64,false><<<BB*HNN, 160>>>(1, 1, wm[1], bq[1], wf[1], bf[1], bm[2], wm[2], wq[2], nullptr);
    k_pair2<64,false><<<BB*HNN, 160>>>(0, 2, wm[2], bq[2], wf[2], bf[2], bm[3], wm[3], wq[3], nullptr);
    k_pair2<64,true ><<<BB*HNN, 160>>>(1, 3, wm[3], bq[3], nullptr, nullptr, nullptr, nullptr, nullptr, out);
}

// round 15
// speedup vs baseline: 1.3079x; 1.3079x over previous
#include <cuda_runtime.h>
#include <math.h>

#define BB 8
#define NN 150
#define SS 22
#define EE 299
#define BN (BB*NN)
#define HNN (NN/2)

// ---------------- persistent scratch (no allocation allowed) ----------------
__device__ __align__(16) float g_h[2][BN*64];
__device__ __align__(16) float g_q[2][BN*4];
__device__ __align__(16) float g_x[2][BN*4];
__device__ __align__(16) float g_A[2][BN*32];
__device__ __align__(16) float g_B[2][BN*32];
__device__ __align__(16) float g_aq[2][BN*6];     // A_i @ Wq (bm folded into A)
__device__ __align__(16) float g_bqv[2][BN*8];    // B_j @ Wq (padded stride 8)
__device__ __align__(16) float g_eq[4][EE*8];     // Wm_E rows @ Wq (padded stride 8)
__device__ __align__(16) float g_Gt[4][72];       // (Wg @ Wq) transposed: [c*12 + r]
__device__ __align__(16) float g_P[4][EE*32];     // scratch: prefix of Wm_E rows
__device__ __align__(16) float g_Esum[4][NN*32];  // per-i window sum of E rows minus diag row

// ---------------- quaternion helpers (match reference exactly) --------------
__device__ __forceinline__ void qmul(const float a[4], const float b[4], float o[4]) {
    o[0] = a[0]*b[0] - a[1]*b[1] - a[2]*b[2] - a[3]*b[3];
    o[1] = a[0]*b[1] + a[1]*b[0] + a[2]*b[3] - a[3]*b[2];
    o[2] = a[0]*b[2] - a[1]*b[3] + a[2]*b[0] + a[3]*b[1];
    o[3] = a[0]*b[3] + a[1]*b[2] - a[2]*b[1] + a[3]*b[0];
}
__device__ __forceinline__ void qrot(const float q[4], const float v[3], float o[3]) {
    float tx = 2.f*(q[2]*v[2] - q[3]*v[1]);
    float ty = 2.f*(q[3]*v[0] - q[1]*v[2]);
    float tz = 2.f*(q[1]*v[1] - q[2]*v[0]);
    o[0] = v[0] + q[0]*tx + (q[2]*tz - q[3]*ty);
    o[1] = v[1] + q[0]*ty + (q[3]*tx - q[1]*tz);
    o[2] = v[2] + q[0]*tz + (q[1]*ty - q[2]*tx);
}

// ---- multi-value butterfly reduction step: keep HALF values, ship HALF ----
template<int O, int HALF>
__device__ __forceinline__ void rstep(float* a, int lane) {
    bool hi = (lane & O) != 0;
    #pragma unroll
    for (int i = 0; i < HALF; i++) {
        float send = hi ? a[i] : a[i+HALF];
        float got = __shfl_xor_sync(0xffffffffu, send, O);
        a[i] = (hi ? a[i+HALF] : a[i]) + got;
    }
}

// ---- dual pair core: nodes i0,i1 vs same j; Gt via float4 broadcast LDS ----
template<bool LAST>
__device__ __forceinline__ void pair_core2(
    const float qi0[4], const float xi0[3],
    const float qi1[4], const float xi1[3],
    const float qj[4],  const float xj[3],
    const float* __restrict__ eq0row, const float* __restrict__ eq1row,
    float4 v0, float4 v1,
    const float* __restrict__ s_aq0, const float* __restrict__ s_aq1,
    const float* __restrict__ bqs, const float* __restrict__ sGt,
    float mmf0, float mmf1, float* acc)
{
    constexpr int NPA = LAST ? 7 : 16;
    constexpr int XO  = LAST ? 0 : 9;

    float qji[4] = {qj[0],-qj[1],-qj[2],-qj[3]};

    float diff0[3] = {xi0[0]-xj[0], xi0[1]-xj[1], xi0[2]-xj[2]};
    float lx0[3]; qrot(qji, diff0, lx0);
    float tq0[4]; qmul(qji, qi0, tq0);
    float lq0[4]; qmul(tq0, qj, lq0);
    float d20 = diff0[0]*diff0[0]+diff0[1]*diff0[1]+diff0[2]*diff0[2];
    float dq0 = fabsf(qi0[0]*qj[0]+qi0[1]*qj[1]+qi0[2]*qj[2]+qi0[3]*qj[3]);
    float geo0[9] = {lx0[0],lx0[1],lx0[2],lq0[0],lq0[1],lq0[2],lq0[3],d20,dq0};

    float diff1[3] = {xi1[0]-xj[0], xi1[1]-xj[1], xi1[2]-xj[2]};
    float lx1[3]; qrot(qji, diff1, lx1);
    float tq1[4]; qmul(qji, qi1, tq1);
    float lq1[4]; qmul(tq1, qj, lq1);
    float d21 = diff1[0]*diff1[0]+diff1[1]*diff1[1]+diff1[2]*diff1[2];
    float dq1 = fabsf(qi1[0]*qj[0]+qi1[1]*qj[1]+qi1[2]*qj[2]+qi1[3]*qj[3]);
    float geo1[9] = {lx1[0],lx1[1],lx1[2],lq1[0],lq1[1],lq1[2],lq1[3],d21,dq1};

    const float4* e0p = reinterpret_cast<const float4*>(eq0row);
    float4 a0 = e0p[0], a1 = e0p[1];
    const float4* e1p = reinterpret_cast<const float4*>(eq1row);
    float4 b0 = e1p[0], b1 = e1p[1];
    float basec0[6] = {a0.x+v0.x, a0.y+v0.y, a0.z+v0.z, a0.w+v0.w, a1.x+v1.x, a1.y+v1.y};
    float basec1[6] = {b0.x+v0.x, b0.y+v0.y, b0.z+v0.z, b0.w+v0.w, b1.x+v1.x, b1.y+v1.y};

    const float4* sg4 = reinterpret_cast<const float4*>(sGt);
    float del0[6], del1[6];
    #pragma unroll
    for (int c = 0; c < 6; c++) {
        float bc = bqs[c];
        float u0 = s_aq0[c] + bc + basec0[c];
        float u1 = s_aq1[c] + bc + basec1[c];
        float4 gA = sg4[c*3], gB = sg4[c*3+1], gC = sg4[c*3+2];
        float g[9] = {gA.x,gA.y,gA.z,gA.w,gB.x,gB.y,gB.z,gB.w,gC.x};
        #pragma unroll
        for (int r = 0; r < 9; r++) {
            u0 = fmaf(geo0[r], g[r], u0);
            u1 = fmaf(geo1[r], g[r], u1);
        }
        del0[c] = u0 * mmf0;
        del1[c] = u1 * mmf1;
    }

    {
        float v3[3] = {lx0[0]+del0[3], lx0[1]+del0[4], lx0[2]+del0[5]};
        float rx[3]; qrot(qj, v3, rx);
        float vq[4] = {0.f, del0[0], del0[1], del0[2]};
        float sq[4]; qmul(lq0, vq, sq);
        if (!LAST) {
            #pragma unroll
            for (int r = 0; r < 9; r++) acc[r] = geo0[r] * mmf0;
        }
        acc[XO+0] = rx[0]+xj[0]; acc[XO+1] = rx[1]+xj[1]; acc[XO+2] = rx[2]+xj[2];
        acc[XO+3] = lq0[0]+sq[0]; acc[XO+4] = lq0[1]+sq[1];
        acc[XO+5] = lq0[2]+sq[2]; acc[XO+6] = lq0[3]+sq[3];
    }
    {
        float* a = acc + NPA;
        float v3[3] = {lx1[0]+del1[3], lx1[1]+del1[4], lx1[2]+del1[5]};
        float rx[3]; qrot(qj, v3, rx);
        float vq[4] = {0.f, del1[0], del1[1], del1[2]};
        float sq[4]; qmul(lq1, vq, sq);
        if (!LAST) {
            #pragma unroll
            for (int r = 0; r < 9; r++) a[r] = geo1[r] * mmf1;
        }
        a[XO+0] = rx[0]+xj[0]; a[XO+1] = rx[1]+xj[1]; a[XO+2] = rx[2]+xj[2];
        a[XO+3] = lq1[0]+sq[0]; a[XO+4] = lq1[1]+sq[1];
        a[XO+5] = lq1[2]+sq[2]; a[XO+6] = lq1[3]+sq[3];
    }
}

// ---------------- merged init + weight prep (R11-style: 4 prep blocks) ------
__global__ void k_initprep(const float* __restrict__ quats, const float* __restrict__ trans,
                           const float* __restrict__ feat, const int* __restrict__ tptr,
                           const float* __restrict__ bm1,
                           const float* wm1, const float* wm2, const float* wm3, const float* wm4,
                           const float* wq1, const float* wq2, const float* wq3, const float* wq4) {
    int t = threadIdx.x; // 128
    if (blockIdx.x < BN) {
        int n = blockIdx.x;
        __shared__ float hs[30];
        __shared__ float sAB[64];
        float tv = tptr ? (float)(*tptr) : 250.0f;
        float ft = tv * (1.0f/1000.0f);
        if (t < 4)  { float v = quats[n*4+t]; g_q[0][n*4+t] = v; g_h[0][n*64+t] = v; hs[t] = v; }
        if (t < 3)  { float v = trans[n*3+t]; g_x[0][n*4+t] = v; g_h[0][n*64+4+t] = v; hs[4+t] = v; }
        if (t == 3) g_x[0][n*4+3] = 0.f;
        if (t < SS) { float v = feat[n*SS+t]; g_h[0][n*64+7+t] = v; hs[7+t] = v; }
        if (t == 0) { g_h[0][n*64+29] = ft; hs[29] = ft; }
        __syncthreads();
        if (t < 64) {
            int k = t & 31;
            float v = (t < 32) ? bm1[k] : 0.f;
            const float* base = wm1 + ((t < 32) ? 0 : 30*32);
            #pragma unroll
            for (int r = 0; r < 30; r++) v = fmaf(hs[r], base[r*32+k], v);
            sAB[t] = v;
            if (t < 32) g_A[0][n*32+k] = v; else g_B[0][n*32+k] = v;
        }
        __syncthreads();
        if (t < 6) {
            float v = 0.f;
            #pragma unroll
            for (int k = 0; k < 32; k++) v = fmaf(sAB[k], wq1[k*6+t], v);
            g_aq[0][n*6+t] = v;
        } else if (t >= 8 && t < 16) {
            int c = t - 8;
            float v = 0.f;
            if (c < 6) {
                #pragma unroll
                for (int k = 0; k < 32; k++) v = fmaf(sAB[32+k], wq1[k*6+c], v);
            }
            g_bqv[0][n*8+c] = v;
        }
    } else {
        int l = blockIdx.x - BN;
        const float* wm = (l==0)?wm1:(l==1)?wm2:(l==2)?wm3:wm4;
        const float* wq = (l==0)?wq1:(l==1)?wq2:(l==2)?wq3:wq4;
        int H = (l==0)?30:64;
        const float* wmE = wm + 2*H*32;
        const float* wg  = wm + (2*H+EE)*32;
        for (int idx = t; idx < EE*6; idx += 128) {
            int r = idx / 6, c = idx - r*6;
            float v = 0.f;
            #pragma unroll
            for (int k = 0; k < 32; k++) v = fmaf(wmE[r*32+k], wq[k*6+c], v);
            g_eq[l][r*8+c] = v;
        }
        for (int r = t; r < EE; r += 128) { g_eq[l][r*8+6] = 0.f; g_eq[l][r*8+7] = 0.f; }
        // Gt transposed+padded: [c*12 + r]
        if (t < 72) {
            int c = t / 12, r = t - c*12;
            float v = 0.f;
            if (r < 9) {
                #pragma unroll
                for (int k = 0; k < 32; k++) v = fmaf(wg[r*32+k], wq[k*6+c], v);
            }
            g_Gt[l][t] = v;
        }
        if (t < 32) {
            float run = 0.f;
            for (int r = 0; r < EE; r++) { run += wmE[r*32+t]; g_P[l][r*32+t] = run; }
        }
        __syncthreads();
        for (int idx = t; idx < NN*32; idx += 128) {
            int i = idx >> 5, k = idx & 31;
            float v = g_P[l][(i+NN-1)*32+k]
                    - (i ? g_P[l][(i-1)*32+k] : 0.f)
                    - wmE[(NN-1)*32+k];
            g_Esum[l][idx] = v;
        }
    }
}

// ---------------- pair kernel: one block per (b, node-pair) ------------------
template<int H, bool LAST>
__global__ void __launch_bounds__(160) k_pair2(int p, int lidx,
    const float* __restrict__ wm,  const float* __restrict__ bq,
    const float* __restrict__ wf,  const float* __restrict__ bf,
    const float* __restrict__ bm2, const float* __restrict__ wm2,
    const float* __restrict__ wq2, float* __restrict__ out)
{
    const int blk = blockIdx.x;                 // 600
    const int b = blk / HNN, ii = blk - b*HNN;
    const int i0 = 2*ii, i1 = i0+1;
    const int node0 = b*NN + i0, node1 = node0+1;
    const int tid = threadIdx.x;

    constexpr int NPA  = LAST ? 7 : 16;
    constexpr int NRED = LAST ? 16 : 32;
    constexpr int NFIN = 2*NPA;
    constexpr int XO   = LAST ? 0 : 9;

    __shared__ float4 qs[NN], xs[NN];
    __shared__ float sA0[32], sBi0[32], sA1[32], sBi1[32];
    __shared__ __align__(16) float sGt[72];
    __shared__ float s_aq0[6], s_aq1[6], bqs[6];
    __shared__ float hs0[64], hs1[64];
    __shared__ float red[5][32];
    __shared__ float fin[32];
    __shared__ float sb[5][32];
    __shared__ float msum0[32], msum1[32];
    __shared__ float hn0[64], hn1[64];
    __shared__ float sAB0[64], sAB1[64];

    // ---- staged loads (R8/R11-proven) ----
    {
        const float4* q4 = reinterpret_cast<const float4*>(g_q[p]) + b*NN;
        const float4* x4 = reinterpret_cast<const float4*>(g_x[p]) + b*NN;
        for (int idx = tid; idx < NN; idx += 160) { qs[idx] = q4[idx]; xs[idx] = x4[idx]; }
    }
    if (tid < 18) reinterpret_cast<float4*>(sGt)[tid] =
        reinterpret_cast<const float4*>(g_Gt[lidx])[tid];
    if (tid >= 64 && tid < 70)  s_aq0[tid-64] = g_aq[p][node0*6+(tid-64)];
    if (tid >= 70 && tid < 76)  s_aq1[tid-70] = g_aq[p][node1*6+(tid-70)];
    if (tid >= 76 && tid < 82)  bqs[tid-76]   = bq[tid-76];
    if (!LAST) {
        if (tid >= 96 && tid < 128) { int k = tid-96;  sA0[k] = g_A[p][node0*32+k]; sBi0[k] = g_B[p][node0*32+k]; }
        if (tid >= 128)             { int k = tid-128; sA1[k] = g_A[p][node1*32+k]; sBi1[k] = g_B[p][node1*32+k]; }
        if (tid < 64)               hs0[tid]    = g_h[p][node0*64+tid];
        else if (tid < 128)         hs1[tid-64] = g_h[p][node1*64+(tid-64)];
    }
    __syncthreads();

    const int w = tid >> 5, lane = tid & 31;
    if (!LAST) {
        // strided per-warp partial sum of all B_j (hoisted: overlaps pair math)
        float bacc = 0.f;
        #pragma unroll 6
        for (int jj = w; jj < NN; jj += 5) bacc += g_B[p][(b*NN+jj)*32 + lane];
        sb[w][lane] = bacc;
    }

    float acc[NRED];
    #pragma unroll
    for (int r = 0; r < NRED; r++) acc[r] = 0.f;

    const int j = tid;
    if (j < NN) {
        float4 qjv = qs[j]; float qj[4] = {qjv.x, qjv.y, qjv.z, qjv.w};
        float4 xjv = xs[j]; float xj[3] = {xjv.x, xjv.y, xjv.z};
        const float4* bvp = reinterpret_cast<const float4*>(&g_bqv[p][(b*NN+j)*8]);
        float4 v0 = bvp[0], v1 = bvp[1];
        const float* eq0 = &g_eq[lidx][(NN-1+i0-j)*8];

        float4 qi0v = qs[i0]; float qi0[4] = {qi0v.x, qi0v.y, qi0v.z, qi0v.w};
        float4 xi0v = xs[i0]; float xi0[3] = {xi0v.x, xi0v.y, xi0v.z};
        float4 qi1v = qs[i1]; float qi1[4] = {qi1v.x, qi1v.y, qi1v.z, qi1v.w};
        float4 xi1v = xs[i1]; float xi1[3] = {xi1v.x, xi1v.y, xi1v.z};

        pair_core2<LAST>(qi0, xi0, qi1, xi1, qj, xj, eq0, eq0 + 8, v0, v1,
                         s_aq0, s_aq1, bqs, sGt,
                         (j == i0) ? 0.f : 1.f, (j == i1) ? 0.f : 1.f, acc);
    }

    // ---- multi-value butterfly reduction (R8-proven) ----
    if (!LAST) {
        rstep<16,16>(acc, lane);
        rstep<8,8>(acc, lane);
        rstep<4,4>(acc, lane);
        rstep<2,2>(acc, lane);
        rstep<1,1>(acc, lane);
        red[w][lane] = acc[0];
    } else {
        #pragma unroll
        for (int i = 0; i < 16; i++) acc[i] += __shfl_xor_sync(0xffffffffu, acc[i], 1);
        rstep<16,8>(acc, lane);
        rstep<8,4>(acc, lane);
        rstep<4,2>(acc, lane);
        rstep<2,1>(acc, lane);
        if (!(lane & 1)) red[w][lane >> 1] = acc[0];
    }
    __syncthreads();
    if (tid < NFIN)
        fin[tid] = red[0][tid]+red[1][tid]+red[2][tid]+red[3][tid]+red[4][tid];
    __syncthreads();

    // ---- q/x finalize: thread 0 -> node0, thread 32 -> node1 ----
    if (tid == 0 || tid == 32) {
        int nloc   = (tid == 0) ? i0 : i1;
        int nodeg  = (tid == 0) ? node0 : node1;
        const float* f = fin + ((tid == 0) ? 0 : NPA);
        float4 qiv = qs[nloc]; float qi[4] = {qiv.x, qiv.y, qiv.z, qiv.w};
        const float invn = 1.0f/(float)(NN-1);
        float ux[3] = {f[XO+0]*invn, f[XO+1]*invn, f[XO+2]*invn};
        float s0=f[XO+3], s1=f[XO+4], s2=f[XO+5], s3=f[XO+6];
        float ns = sqrtf(s0*s0+s1*s1+s2*s2+s3*s3);
        float inv = 1.f / fmaxf(ns, 1e-12f);
        float luq[4] = {s0*inv, s1*inv, s2*inv, s3*inv};
        float t1[4]; qmul(qi, luq, t1);
        float qc[4] = {qi[0],-qi[1],-qi[2],-qi[3]};
        float uq[4]; qmul(t1, qc, uq);
        if (LAST) {
            out[nodeg*7+0]=uq[0]; out[nodeg*7+1]=uq[1];
            out[nodeg*7+2]=uq[2]; out[nodeg*7+3]=uq[3];
            out[nodeg*7+4]=ux[0]; out[nodeg*7+5]=ux[1]; out[nodeg*7+6]=ux[2];
        } else {
            int nb = p^1;
            g_q[nb][nodeg*4+0]=uq[0]; g_q[nb][nodeg*4+1]=uq[1];
            g_q[nb][nodeg*4+2]=uq[2]; g_q[nb][nodeg*4+3]=uq[3];
            g_x[nb][nodeg*4+0]=ux[0]; g_x[nb][nodeg*4+1]=ux[1];
            g_x[nb][nodeg*4+2]=ux[2]; g_x[nb][nodeg*4+3]=0.f;
        }
    }

    if (!LAST) {
        // ---- E1: msum for both nodes (64 threads) ----
        if (tid < 64) {
            int k = tid & 31;
            bool n1 = (tid >= 32);
            const float* sA  = n1 ? sA1  : sA0;
            const float* sBi = n1 ? sBi1 : sBi0;
            const float* f   = fin + (n1 ? NPA : 0);
            int irow = n1 ? i1 : i0;
            float sB = sb[0][k]+sb[1][k]+sb[2][k]+sb[3][k]+sb[4][k];
            float v = (float)(NN-1)*sA[k] + (sB - sBi[k]) + g_Esum[lidx][irow*32+k];
            const float* wg = wm + (2*H+EE)*32;
            #pragma unroll
            for (int r = 0; r < 9; r++) v = fmaf(f[r], wg[r*32+k], v);
            (n1 ? msum1 : msum0)[k] = v;
        }
        __syncthreads();
        // ---- E2: o = [h, msum] @ Wf + bf -> relu (128 threads, ILP4) ----
        if (tid < 128) {
            int c = tid & 63;
            bool n1 = (tid >= 64);
            const float* hsrc = n1 ? hs1 : hs0;
            const float* msrc = n1 ? msum1 : msum0;
            float a0 = bf[c], a1 = 0.f, a2 = 0.f, a3 = 0.f;
            int r = 0;
            #pragma unroll
            for (; r + 4 <= H; r += 4) {
                a0 = fmaf(hsrc[r+0], wf[(r+0)*64+c], a0);
                a1 = fmaf(hsrc[r+1], wf[(r+1)*64+c], a1);
                a2 = fmaf(hsrc[r+2], wf[(r+2)*64+c], a2);
                a3 = fmaf(hsrc[r+3], wf[(r+3)*64+c], a3);
            }
            #pragma unroll
            for (; r < H; r++) a0 = fmaf(hsrc[r], wf[r*64+c], a0);
            #pragma unroll
            for (int k = 0; k < 32; k += 4) {
                a0 = fmaf(msrc[k+0], wf[(H+k+0)*64+c], a0);
                a1 = fmaf(msrc[k+1], wf[(H+k+1)*64+c], a1);
                a2 = fmaf(msrc[k+2], wf[(H+k+2)*64+c], a2);
                a3 = fmaf(msrc[k+3], wf[(H+k+3)*64+c], a3);
            }
            float hv = fmaxf((a0+a2)+(a1+a3), 0.f);
            int nodeg = n1 ? node1 : node0;
            (n1 ? hn1 : hn0)[c] = hv;
            g_h[p^1][nodeg*64+c] = hv;
        }
        __syncthreads();
        // ---- E3: A'/B' (128 threads, ILP2) ----
        if (tid < 128) {
            int k = tid & 31;
            bool isB = (tid & 32);
            bool n1 = (tid >= 64);
            const float* h = n1 ? hn1 : hn0;
            float u0 = isB ? 0.f : bm2[k], u1 = 0.f;
            const float* base = wm2 + (isB ? 64*32 : 0);
            #pragma unroll
            for (int r = 0; r < 64; r += 2) {
                u0 = fmaf(h[r+0], base[(r+0)*32+k], u0);
                u1 = fmaf(h[r+1], base[(r+1)*32+k], u1);
            }
            float v = u0 + u1;
            int nodeg = n1 ? node1 : node0;
            float* sAB = n1 ? sAB1 : sAB0;
            sAB[isB ? 32+k : k] = v;
            if (isB) g_B[p^1][nodeg*32+k] = v; else g_A[p^1][nodeg*32+k] = v;
        }
        __syncthreads();
        // ---- E4: aq' / bqv' (ILP2) ----
        {
            int base = tid & 63;
            bool n1 = (tid >= 64);
            if (tid < 128) {
                const float* sAB = n1 ? sAB1 : sAB0;
                int nodeg = n1 ? node1 : node0;
                if (base < 6) {
                    float u0 = 0.f, u1 = 0.f;
                    #pragma unroll
                    for (int k = 0; k < 32; k += 2) {
                        u0 = fmaf(sAB[k+0], wq2[(k+0)*6+base], u0);
                        u1 = fmaf(sAB[k+1], wq2[(k+1)*6+base], u1);
                    }
                    g_aq[p^1][nodeg*6+base] = u0 + u1;
                } else if (base >= 8 && base < 16) {
                    int c = base - 8;
                    float v = 0.f;
                    if (c < 6) {
                        float u0 = 0.f, u1 = 0.f;
                        #pragma unroll
                        for (int k = 0; k < 32; k += 2) {
                            u0 = fmaf(sAB[32+k+0], wq2[(k+0)*6+c], u0);
                            u1 = fmaf(sAB[32+k+1], wq2[(k+1)*6+c], u1);
                        }
                        v = u0 + u1;
                    }
                    g_bqv[p^1][nodeg*8+c] = v;
                }
            }
        }
    }
}

// ---------------- host launcher ---------------------------------------------
extern "C" void kernel_launch(void* const* d_in, const int* in_sizes, int n_in,
                              void* d_out, int out_size) {
    const float *quats = nullptr, *trans = nullptr, *feats = nullptr;
    const int* tptr = nullptr;
    int wmI[4] = {-1,-1,-1,-1};
    int maskIdx = -1;
    int n13952 = 0;
    for (int idx = 0; idx < n_in; idx++) {
        int s = in_sizes[idx];
        if      (s == 4800)  quats = (const float*)d_in[idx];
        else if (s == 3600)  trans = (const float*)d_in[idx];
        else if (s == 26400) feats = (const float*)d_in[idx];
        else if (s == 1200)  maskIdx = idx;
        else if (s == 11776) wmI[0] = idx;
        else if (s == 13952 && n13952 < 3) { wmI[1+n13952] = idx; n13952++; }
    }
    if (maskIdx >= 0 && maskIdx+1 < n_in && in_sizes[maskIdx+1] == 1)
        tptr = (const int*)d_in[maskIdx+1];

    const float *wm[4], *bm[4], *wf[4], *bf[4], *wq[4], *bq[4];
    for (int l = 0; l < 4; l++) {
        int base = wmI[l];
        wm[l] = (const float*)d_in[base+0];
        bm[l] = (const float*)d_in[base+1];
        wf[l] = (const float*)d_in[base+2];
        bf[l] = (const float*)d_in[base+3];
        wq[l] = (const float*)d_in[base+4];
        bq[l] = (const float*)d_in[base+5];
    }
    float* out = (float*)d_out;

    k_initprep<<<BN+4, 128>>>(quats, trans, feats, tptr, bm[0],
                              wm[0], wm[1], wm[2], wm[3],
                              wq[0], wq[1], wq[2], wq[3]);

    k_pair2<30,false><<<BB*HNN, 160>>>(0, 0, wm[0], bq[0], wf[0], bf[0], bm[1], wm[1], wq[1], nullptr);
    k_pair2<64,false><<<BB*HNN, 160>>>(1, 1, wm[1], bq[1], wf[1], bf[1], bm[2], wm[2], wq[2], nullptr);
    k_pair2<64,false><<<BB*HNN, 160>>>(0, 2, wm[2], bq[2], wf[2], bf[2], bm[3], wm[3], wq[3], nullptr);
    k_pair2<64,true ><<<BB*HNN, 160>>>(1, 3, wm[3], bq[3], nullptr, nullptr, nullptr, nullptr, nullptr, out);
}